// round 16
// baseline (speedup 1.0000x reference)
#include <cuda_runtime.h>
#include <cstdint>

#define NMAX 100000
#define EMAX 1600000
#define CDIV(a,b) (((a)+(b)-1)/(b))
#define AGG_BLOCKS 1184  // 148 SMs x 8 CTAs: single-wave persistent aggregation
#define NB 512           // k_graph persistent blocks (512 thr each; single wave)

// ---------------- scratch (static device globals; no runtime alloc) ----------------
__device__ float g_bufA[NMAX*128];   // node features (layer input / agg output)
__device__ float g_bufB[NMAX*128];   // GEMM output (pre-aggregation)
__device__ int   g_cnt[NMAX];
__device__ int   g_rowptr[NMAX+1];
__device__ int2  g_edge[EMAX];       // packed {src, norm-weight bits}
__device__ float g_dis[NMAX];        // rsqrt(deg)
__device__ float g_invdeg[NMAX];     // 1/deg  (self-loop norm)
__device__ int   g_bsum[NB];         // per-block count sums
__device__ float g_stats[256];       // [0:128) sum, [128:256) sumsq
__device__ float g_scale[128];
__device__ float g_shift[128];
__device__ int   g_is64;
__device__ int   g_done;             // agg completion ticket (returns to 0 per use)
__device__ int   g_bar;              // k_graph grid-barrier counter (init zeroes)
// bf16-split weights, fragment-ordered, triple-buffered: w0@0, w1@8192, w2@16384
__device__ __align__(16) unsigned g_wfh[20480];
__device__ __align__(16) unsigned g_wfl[20480];

// ---------------- bf16 helpers ----------------
__device__ __forceinline__ unsigned pack_bf16(float lo, float hi){
    unsigned r; asm("cvt.rn.bf16x2.f32 %0, %1, %2;" : "=r"(r) : "f"(hi), "f"(lo)); return r;
}
__device__ __forceinline__ float bf_lo(unsigned p){ return __uint_as_float(p << 16); }
__device__ __forceinline__ float bf_hi(unsigned p){ return __uint_as_float(p & 0xFFFF0000u); }

__device__ __forceinline__ void mma_bf16(float* d, const unsigned* a, const unsigned* b){
    asm volatile("mma.sync.aligned.m16n8k16.row.col.f32.bf16.bf16.f32 "
        "{%0,%1,%2,%3}, {%4,%5,%6,%7}, {%8,%9}, {%0,%1,%2,%3};"
        : "+f"(d[0]),"+f"(d[1]),"+f"(d[2]),"+f"(d[3])
        : "r"(a[0]),"r"(a[1]),"r"(a[2]),"r"(a[3]), "r"(b[0]),"r"(b[1]));
}

// ---------------- edge index access (int64 vs int32, detected on device) -----------
__device__ __forceinline__ long long edge_at(const void* ei, long long idx, int is64){
    return is64 ? ((const long long*)ei)[idx] : (long long)((const int*)ei)[idx];
}

// ---------------- grid barrier (monotonic ticket; single-wave kernels ONLY) --------
__device__ __forceinline__ void grid_bar(int target){
    __syncthreads();
    if (threadIdx.x == 0){
        __threadfence();
        atomicAdd(&g_bar, 1);
        while (atomicAdd(&g_bar, 0) < target) __nanosleep(64);
    }
    __syncthreads();
}

// ---------------- weight split into fragment-ordered bf16 hi/lo ----------------
// W is [128][DOUT] row-major. Fragments for mma.m16n8k16.row.col:
// b0 = W[k16*16 + 2t + {0,1}][n], b1 = W[k16*16 + 2t + 8 + {0,1}][n], lane=(n&7)*4+t
template<int DOUT>
__device__ __forceinline__ void wsplit_one(const float* __restrict__ W, int idx, int base){
    constexpr int NT = DOUT/8;
    int kp = idx / DOUT;          // 0..63
    int nn = idx % DOUT;
    int k  = kp*2;
    float f0 = W[(size_t)k*DOUT + nn];
    float f1 = W[(size_t)(k+1)*DOUT + nn];
    unsigned h = pack_bf16(f0, f1);
    unsigned l = pack_bf16(f0 - bf_lo(h), f1 - bf_hi(h));
    int kk  = k & 15;
    int reg = kk >> 3;
    int t   = (kk >> 1) & 3;
    int k16 = k >> 4;
    int g   = nn & 7, nt = nn >> 3;
    int pos = (((k16*NT + nt)*32) + g*4 + t)*2 + reg;
    g_wfh[base + pos] = h;
    g_wfl[base + pos] = l;
}

// ---------------- init: zero cnt/stats/bar + is64 detect + wsplit(w0,w1,w2) --------
__global__ void k_init(const void* ei, const float* __restrict__ w0,
                       const float* __restrict__ w1, const float* __restrict__ w2, int n){
    int b = blockIdx.x, tid = threadIdx.x;
    int zb = (n + 255) >> 8;                 // blocks dedicated to cnt-zeroing
    if (b < zb){
        int i = b*256 + tid;
        if (i < n) g_cnt[i] = 0;
        if (b == 0){ g_stats[tid] = 0.f; if (tid == 0){ g_done = 0; g_bar = 0; } }
    } else {
        int j = (b - zb)*256 + tid;          // 0..20479 (80 blocks)
        if (j < 8192)       wsplit_one<128>(w0, j,          0);
        else if (j < 16384) wsplit_one<128>(w1, j - 8192,   8192);
        else                wsplit_one<64>(w2, j - 16384,  16384);
        if (b == zb && tid < 32){
            const int* p = (const int*)ei;
            int bad = 0;
            #pragma unroll
            for (int k = tid; k < 128; k += 32) bad |= (p[2*k+1] != 0);
            unsigned m = __ballot_sync(0xffffffffu, bad);
            if (tid == 0) g_is64 = (m == 0);   // ids < 2^31 -> high words zero iff int64
        }
    }
}

// ---------------- FUSED graph build: hist + scan + deg + fill, one kernel ----------
// NB=512 blocks x 512 thr (4 CTAs/SM, single wave; grid barriers safe).
__global__ void __launch_bounds__(512) k_graph(const void* ei, int n, int E){
    __shared__ int sh[512], sh2[512];
    int tid = threadIdx.x, b = blockIdx.x;
    int is64 = g_is64;

    // ---- phase 0: degree histogram (grid-stride, 262144 threads) ----
    for (int e = b*512 + tid; e < E; e += NB*512){
        int d = (int)edge_at(ei, (long long)E + e, is64);
        atomicAdd(&g_cnt[d], 1);
    }
    grid_bar(NB);

    // ---- phase A: per-block chunk sums (PT contiguous nodes per thread) ----
    int CH = CDIV(n, NB);                 // nodes per block (196 for n=100k)
    int PT = CDIV(CH, 512);               // nodes per thread (1 for n=100k)
    int base = b*CH;
    int i0 = base + tid*PT;
    int c0 = 0, c1 = 0;
    if (i0 < n && tid*PT < CH) c0 = g_cnt[i0];
    if (PT > 1 && i0+1 < n && tid*PT+1 < CH) c1 = g_cnt[i0+1];
    sh[tid] = c0 + c1;
    __syncthreads();
    #pragma unroll
    for (int off = 256; off; off >>= 1){
        if (tid < off) sh[tid] += sh[tid + off];
        __syncthreads();
    }
    if (tid == 0) g_bsum[b] = sh[0];
    grid_bar(2*NB);

    // ---- phase B: scan block sums + block-local scan -> rowptr, deg, cnt=0 ----
    sh[tid] = g_bsum[tid];                // NB == blockDim
    __syncthreads();
    #pragma unroll
    for (int off = 1; off < 512; off <<= 1){
        int v = (tid >= off) ? sh[tid - off] : 0;
        __syncthreads();
        sh[tid] += v;
        __syncthreads();
    }
    int blockBase = sh[b] - g_bsum[b];    // exclusive prefix for this block
    __syncthreads();
    sh2[tid] = c0 + c1;
    __syncthreads();
    #pragma unroll
    for (int off = 1; off < 512; off <<= 1){
        int v = (tid >= off) ? sh2[tid - off] : 0;
        __syncthreads();
        sh2[tid] += v;
        __syncthreads();
    }
    int tex = blockBase + sh2[tid] - (c0 + c1);   // exclusive offset for i0
    if (i0 < n && tid*PT < CH){
        g_rowptr[i0] = tex;
        g_cnt[i0] = 0;
        float cf = (float)(c0 + 1);
        g_dis[i0]    = rsqrtf(cf);
        g_invdeg[i0] = 1.0f / cf;
        int i1 = i0 + 1;
        if (PT > 1 && i1 < n && tid*PT+1 < CH){
            g_rowptr[i1] = tex + c0;
            g_cnt[i1] = 0;
            float cf1 = (float)(c1 + 1);
            g_dis[i1]    = rsqrtf(cf1);
            g_invdeg[i1] = 1.0f / cf1;
        }
    }
    if (b == 0 && tid == 0) g_rowptr[n] = E;
    grid_bar(3*NB);

    // ---- phase C: fill CSR (grid-stride; packed 8B payload) ----
    for (int e = b*512 + tid; e < E; e += NB*512){
        int s = (int)edge_at(ei, e, is64);
        int d = (int)edge_at(ei, (long long)E + e, is64);
        int pos = g_rowptr[d] + atomicAdd(&g_cnt[d], 1);
        g_edge[pos] = make_int2(s, __float_as_int(g_dis[s] * g_dis[d]));
    }
}

// ---------------- GEMM: C(n x DOUT) = relu(bn(A)) @ W via bf16x3 mma.sync ----------
// A tile staged as PACKED bf16x2 hi/lo fragments (2 x 128x68 uint, 69.6KB smem),
// converted during the global load; ONE sync; mainloop = pure LDS.32 + MMA.
// D += Ahi*Whi + Ahi*Wlo + Alo*Whi  (fp32 accum; dropped lo*lo ~ 2^-18)
template<int DOUT, int ASEL, int WBASE>
__global__ void __launch_bounds__(256, 2) k_gemm_bf(const float* __restrict__ Aext, int n){
    constexpr int NT   = DOUT/8;
    constexpr int NTW  = NT/2;                // n-tiles per warp (8 or 4)
    constexpr int LDA2 = 68;                  // uint stride; 68 mod 32 = 4 -> conflict-free
    extern __shared__ unsigned sm[];          // 2 * 128*68*4 = 69632 B
    unsigned* Ahi = sm;
    unsigned* Alo = sm + 128*LDA2;

    const float* A = (ASEL==0) ? Aext : g_bufA;
    int tid = threadIdx.x, lane = tid & 31, warp = tid >> 5;
    int wm = warp >> 1, wn = warp & 1;
    int g = lane >> 2, t = lane & 3;
    int rowBase = blockIdx.x * 128;

    float acc[2][NTW][4];
    #pragma unroll
    for (int a=0;a<2;a++)
        #pragma unroll
        for (int b=0;b<NTW;b++)
            #pragma unroll
            for (int c=0;c<4;c++) acc[a][b][c] = 0.f;

    // ---- full A tile: load, (BN+ReLU), split to packed bf16 hi/lo ----
    #pragma unroll
    for (int i=0;i<16;i++){
        int idx  = tid + i*256;           // 0..4095
        int r    = idx >> 5;              // 0..127
        int c4   = idx & 31;              // float4 within 128 cols
        int grow = rowBase + r;
        float4 v = make_float4(0.f,0.f,0.f,0.f);
        if (grow < n) v = *(const float4*)&A[(size_t)grow*128 + c4*4];
        if (ASEL == 1){
            float4 sc = *(const float4*)&g_scale[c4*4];
            float4 sh = *(const float4*)&g_shift[c4*4];
            v.x = fmaxf(fmaf(v.x, sc.x, sh.x), 0.f);
            v.y = fmaxf(fmaf(v.y, sc.y, sh.y), 0.f);
            v.z = fmaxf(fmaf(v.z, sc.z, sh.z), 0.f);
            v.w = fmaxf(fmaf(v.w, sc.w, sh.w), 0.f);
        }
        unsigned h0 = pack_bf16(v.x, v.y);
        unsigned h1 = pack_bf16(v.z, v.w);
        unsigned l0 = pack_bf16(v.x - bf_lo(h0), v.y - bf_hi(h0));
        unsigned l1 = pack_bf16(v.z - bf_lo(h1), v.w - bf_hi(h1));
        *(uint2*)&Ahi[r*LDA2 + c4*2] = make_uint2(h0, h1);
        *(uint2*)&Alo[r*LDA2 + c4*2] = make_uint2(l0, l1);
    }
    __syncthreads();

    const uint2* WH = (const uint2*)(g_wfh + WBASE);
    const uint2* WL = (const uint2*)(g_wfl + WBASE);

    #pragma unroll
    for (int k16 = 0; k16 < 8; k16++){
        unsigned ah[2][4], al[2][4];
        #pragma unroll
        for (int mt=0; mt<2; mt++){
            int r0 = wm*32 + mt*16 + g;
            #pragma unroll
            for (int q=0; q<4; q++){
                int rr = r0 + (q & 1)*8;
                int ci = k16*8 + t + (q >> 1)*4;
                ah[mt][q] = Ahi[rr*LDA2 + ci];
                al[mt][q] = Alo[rr*LDA2 + ci];
            }
        }
        #pragma unroll
        for (int nt=0; nt<NTW; nt++){
            int off = (k16*NT + wn*NTW + nt)*32 + lane;
            uint2 bh = __ldg(&WH[off]);
            uint2 bl = __ldg(&WL[off]);
            unsigned bhv[2] = {bh.x, bh.y};
            unsigned blv[2] = {bl.x, bl.y};
            #pragma unroll
            for (int mt=0; mt<2; mt++){
                mma_bf16(acc[mt][nt], ah[mt], bhv);
                mma_bf16(acc[mt][nt], ah[mt], blv);
                mma_bf16(acc[mt][nt], al[mt], bhv);
            }
        }
    }

    // ---- store C -> g_bufB ----
    #pragma unroll
    for (int mt=0; mt<2; mt++){
        #pragma unroll
        for (int nt=0; nt<NTW; nt++){
            int col = (wn*NTW + nt)*8 + t*2;
            int r0  = rowBase + wm*32 + mt*16 + g;
            if (r0 < n)
                *(float2*)&g_bufB[(size_t)r0*DOUT + col] =
                    make_float2(acc[mt][nt][0], acc[mt][nt][1]);
            if (r0 + 8 < n)
                *(float2*)&g_bufB[(size_t)(r0+8)*DOUT + col] =
                    make_float2(acc[mt][nt][2], acc[mt][nt][3]);
        }
    }
}

// ---------------- aggregation: PERSISTENT single-wave (8 CTA/SM) + BN stats --------
template<int D>
__global__ void __launch_bounds__(256, 8) k_agg(const float* __restrict__ gw,
                                                const float* __restrict__ be, int n){
    constexpr int F   = D/4;        // float4 per row (32 or 16)
    constexpr int NPW = 32/F;       // nodes per warp-slot (1 or 2)
    __shared__ float ss[128], sq[128];
    __shared__ int isLast;
    int tid = threadIdx.x;
    if (tid < D){ ss[tid] = 0.f; sq[tid] = 0.f; }
    __syncthreads();

    int lane  = tid & 31;
    int gwarp = (blockIdx.x*256 + tid) >> 5;
    int nwarp = (gridDim.x*256) >> 5;
    int fi    = lane % F;
    int sub   = lane / F;

    const float4* t = (const float4*)g_bufB;
    float4* o = (float4*)g_bufA;

    float l0=0.f,l1=0.f,l2=0.f,l3=0.f, q0=0.f,q1=0.f,q2=0.f,q3=0.f;

    for (int node = gwarp*NPW + sub; node < n; node += nwarp*NPW){
        float idg = g_invdeg[node];
        float4 v = t[(size_t)node*F + fi];
        float4 acc = make_float4(v.x*idg, v.y*idg, v.z*idg, v.w*idg);

        int p0 = g_rowptr[node], p1 = g_rowptr[node+1];
        int p = p0;
        for (; p + 1 < p1; p += 2){
            int2 e0 = g_edge[p], e1 = g_edge[p+1];
            float w0 = __int_as_float(e0.y), w1 = __int_as_float(e1.y);
            float4 u0 = t[(size_t)e0.x*F + fi];
            float4 u1 = t[(size_t)e1.x*F + fi];
            acc.x = fmaf(w0,u0.x, fmaf(w1,u1.x, acc.x));
            acc.y = fmaf(w0,u0.y, fmaf(w1,u1.y, acc.y));
            acc.z = fmaf(w0,u0.z, fmaf(w1,u1.z, acc.z));
            acc.w = fmaf(w0,u0.w, fmaf(w1,u1.w, acc.w));
        }
        if (p < p1){
            int2 e0 = g_edge[p];
            float w0 = __int_as_float(e0.y);
            float4 u0 = t[(size_t)e0.x*F + fi];
            acc.x = fmaf(w0,u0.x, acc.x);
            acc.y = fmaf(w0,u0.y, acc.y);
            acc.z = fmaf(w0,u0.z, acc.z);
            acc.w = fmaf(w0,u0.w, acc.w);
        }
        o[(size_t)node*F + fi] = acc;

        l0 += acc.x; q0 += acc.x*acc.x;
        l1 += acc.y; q1 += acc.y*acc.y;
        l2 += acc.z; q2 += acc.z*acc.z;
        l3 += acc.w; q3 += acc.w*acc.w;
    }

    int ch = fi*4;
    atomicAdd(&ss[ch+0], l0); atomicAdd(&sq[ch+0], q0);
    atomicAdd(&ss[ch+1], l1); atomicAdd(&sq[ch+1], q1);
    atomicAdd(&ss[ch+2], l2); atomicAdd(&sq[ch+2], q2);
    atomicAdd(&ss[ch+3], l3); atomicAdd(&sq[ch+3], q3);
    __syncthreads();
    if (tid < D){
        atomicAdd(&g_stats[tid],       ss[tid]);
        atomicAdd(&g_stats[128 + tid], sq[tid]);
    }
    __syncthreads();

    // ---- last-block BN finalize (threadfence-reduction pattern) ----
    if (tid == 0){
        __threadfence();
        isLast = (atomicAdd(&g_done, 1) == (int)gridDim.x - 1);
    }
    __syncthreads();
    if (isLast){
        if (tid < D){
            float s = atomicAdd(&g_stats[tid],       0.f);   // coherent read
            float q = atomicAdd(&g_stats[128 + tid], 0.f);
            float inv_n = 1.0f / (float)n;
            float mu  = s * inv_n;
            float var = q * inv_n - mu*mu;
            float sc  = gw[tid] * rsqrtf(var + 1e-5f);
            g_scale[tid] = sc;
            g_shift[tid] = be[tid] - mu*sc;
            g_stats[tid] = 0.f;              // ready for next layer
            g_stats[128 + tid] = 0.f;
        }
        if (tid == 0) g_done = 0;
    }
}

// ---------------- head: 2-layer MLP (reads g_scale/g_shift from agg<64>) -----------
__global__ void __launch_bounds__(256) k_head(const float* __restrict__ wc1,
                                              const float* __restrict__ bc1,
                                              const float* __restrict__ wc2,
                                              const float* __restrict__ bc2,
                                              float* __restrict__ out, int n){
    __shared__ float w1s[64*32];
    __shared__ float b1s[32], w2s[32], scs[64], shs[64];
    int tid = threadIdx.x;
    for (int i = tid; i < 64*32; i += 256) w1s[i] = wc1[i];
    if (tid < 32){ b1s[tid] = bc1[tid]; w2s[tid] = wc2[tid]; }
    if (tid < 64){ scs[tid] = g_scale[tid]; shs[tid] = g_shift[tid]; }
    __syncthreads();

    int warp = (blockIdx.x*256 + tid) >> 5;
    int lane = tid & 31;
    if (warp >= n) return;

    const float* row = &g_bufA[(size_t)warp * 64];
    float a0 = b1s[lane], a1 = 0.f, a2 = 0.f, a3 = 0.f;
    #pragma unroll
    for (int k = 0; k < 64; k += 4){
        float v0 = fmaxf(fmaf(row[k+0], scs[k+0], shs[k+0]), 0.f);
        float v1 = fmaxf(fmaf(row[k+1], scs[k+1], shs[k+1]), 0.f);
        float v2 = fmaxf(fmaf(row[k+2], scs[k+2], shs[k+2]), 0.f);
        float v3 = fmaxf(fmaf(row[k+3], scs[k+3], shs[k+3]), 0.f);
        a0 = fmaf(v0, w1s[(k+0)*32 + lane], a0);
        a1 = fmaf(v1, w1s[(k+1)*32 + lane], a1);
        a2 = fmaf(v2, w1s[(k+2)*32 + lane], a2);
        a3 = fmaf(v3, w1s[(k+3)*32 + lane], a3);
    }
    float h = fmaxf((a0+a1)+(a2+a3), 0.f) * w2s[lane];
    #pragma unroll
    for (int off = 16; off; off >>= 1) h += __shfl_xor_sync(0xffffffff, h, off);
    if (lane == 0) out[warp] = h + bc2[0];
}

// ---------------- launch ----------------
extern "C" void kernel_launch(void* const* d_in, const int* in_sizes, int n_in,
                              void* d_out, int out_size){
    const float* x   = (const float*)d_in[0];
    const void*  ei  = d_in[1];
    const float* w0  = (const float*)d_in[2];
    const float* g0  = (const float*)d_in[4];
    const float* be0 = (const float*)d_in[5];
    const float* w1  = (const float*)d_in[6];
    const float* g1  = (const float*)d_in[8];
    const float* be1 = (const float*)d_in[9];
    const float* w2  = (const float*)d_in[10];
    const float* g2  = (const float*)d_in[12];
    const float* be2 = (const float*)d_in[13];
    const float* wc1 = (const float*)d_in[14];
    const float* bc1 = (const float*)d_in[15];
    const float* wc2 = (const float*)d_in[16];
    const float* bc2 = (const float*)d_in[17];
    float* out = (float*)d_out;

    int n = in_sizes[0] / 128;
    int E = in_sizes[1] / 2;

    const int GSMEM = 2*128*68*4;    // 69632 B
    cudaFuncSetAttribute(k_gemm_bf<128,0,0>,     cudaFuncAttributeMaxDynamicSharedMemorySize, GSMEM);
    cudaFuncSetAttribute(k_gemm_bf<128,1,8192>,  cudaFuncAttributeMaxDynamicSharedMemorySize, GSMEM);
    cudaFuncSetAttribute(k_gemm_bf<64,1,16384>,  cudaFuncAttributeMaxDynamicSharedMemorySize, GSMEM);

    int zb = CDIV(n,256);
    int gemmGrid = CDIV(n, 128);

    // 9 launches, single stream; my #4 = k_agg<128> (ncu -s 5 -c 1 lands there)
    k_init<<<zb + 80, 256>>>(ei, w0, w1, w2, n);                 // 1
    k_graph<<<NB,512>>>(ei, n, E);                               // 2 (hist+scan+deg+fill)
    k_gemm_bf<128,0,0><<<gemmGrid,256,GSMEM>>>(x, n);            // 3

    // ---- layer 0 ----
    k_agg<128><<<AGG_BLOCKS,256>>>(g0, be0, n);                  // 4 <- profiled

    // ---- layer 1 ----
    k_gemm_bf<128,1,8192><<<gemmGrid,256,GSMEM>>>(nullptr, n);   // 5
    k_agg<128><<<AGG_BLOCKS,256>>>(g1, be1, n);                  // 6

    // ---- layer 2 ----
    k_gemm_bf<64,1,16384><<<gemmGrid,256,GSMEM>>>(nullptr, n);   // 7
    k_agg<64><<<AGG_BLOCKS,256>>>(g2, be2, n);                   // 8

    // ---- head ----
    k_head<<<CDIV(n*32,256),256>>>(wc1, bc1, wc2, bc2, out, n);  // 9
}

// round 17
// speedup vs baseline: 1.1246x; 1.1246x over previous
#include <cuda_runtime.h>
#include <cstdint>

#define NMAX 100000
#define EMAX 1600000
#define CDIV(a,b) (((a)+(b)-1)/(b))
#define AGG_BLOCKS 888   // 148 SMs x 6 CTAs: measured optimum (R15/R16 occupancy curve)
#define NB 512           // k_graph persistent blocks (512 thr each; single wave)

// ---------------- scratch (static device globals; no runtime alloc) ----------------
__device__ float g_bufA[NMAX*128];   // node features (layer input / agg output)
__device__ float g_bufB[NMAX*128];   // GEMM output, pre-scaled by dis[row]
__device__ int   g_cnt[NMAX];
__device__ int   g_rowptr[NMAX+1];
__device__ int   g_ecol[EMAX];       // edge source column only (4B; weights folded away)
__device__ float g_dis[NMAX];        // rsqrt(deg)
__device__ int   g_bsum[NB];         // per-block count sums
__device__ float g_stats[256];       // [0:128) sum, [128:256) sumsq
__device__ float g_scale[128];
__device__ float g_shift[128];
__device__ int   g_is64;
__device__ int   g_done;             // agg completion ticket (returns to 0 per use)
__device__ int   g_bar;              // k_graph grid-barrier counter (init zeroes)
// bf16-split weights, fragment-ordered, triple-buffered: w0@0, w1@8192, w2@16384
__device__ __align__(16) unsigned g_wfh[20480];
__device__ __align__(16) unsigned g_wfl[20480];

// ---------------- bf16 helpers ----------------
__device__ __forceinline__ unsigned pack_bf16(float lo, float hi){
    unsigned r; asm("cvt.rn.bf16x2.f32 %0, %1, %2;" : "=r"(r) : "f"(hi), "f"(lo)); return r;
}
__device__ __forceinline__ float bf_lo(unsigned p){ return __uint_as_float(p << 16); }
__device__ __forceinline__ float bf_hi(unsigned p){ return __uint_as_float(p & 0xFFFF0000u); }

__device__ __forceinline__ void mma_bf16(float* d, const unsigned* a, const unsigned* b){
    asm volatile("mma.sync.aligned.m16n8k16.row.col.f32.bf16.bf16.f32 "
        "{%0,%1,%2,%3}, {%4,%5,%6,%7}, {%8,%9}, {%0,%1,%2,%3};"
        : "+f"(d[0]),"+f"(d[1]),"+f"(d[2]),"+f"(d[3])
        : "r"(a[0]),"r"(a[1]),"r"(a[2]),"r"(a[3]), "r"(b[0]),"r"(b[1]));
}

// ---------------- edge index access (int64 vs int32, detected on device) -----------
__device__ __forceinline__ long long edge_at(const void* ei, long long idx, int is64){
    return is64 ? ((const long long*)ei)[idx] : (long long)((const int*)ei)[idx];
}

// ---------------- grid barrier (monotonic ticket; single-wave kernels ONLY) --------
__device__ __forceinline__ void grid_bar(int target){
    __syncthreads();
    if (threadIdx.x == 0){
        __threadfence();
        atomicAdd(&g_bar, 1);
        while (atomicAdd(&g_bar, 0) < target) __nanosleep(64);
    }
    __syncthreads();
}

// ---------------- weight split into fragment-ordered bf16 hi/lo ----------------
// W is [128][DOUT] row-major. Fragments for mma.m16n8k16.row.col:
// b0 = W[k16*16 + 2t + {0,1}][n], b1 = W[k16*16 + 2t + 8 + {0,1}][n], lane=(n&7)*4+t
template<int DOUT>
__device__ __forceinline__ void wsplit_one(const float* __restrict__ W, int idx, int base){
    constexpr int NT = DOUT/8;
    int kp = idx / DOUT;          // 0..63
    int nn = idx % DOUT;
    int k  = kp*2;
    float f0 = W[(size_t)k*DOUT + nn];
    float f1 = W[(size_t)(k+1)*DOUT + nn];
    unsigned h = pack_bf16(f0, f1);
    unsigned l = pack_bf16(f0 - bf_lo(h), f1 - bf_hi(h));
    int kk  = k & 15;
    int reg = kk >> 3;
    int t   = (kk >> 1) & 3;
    int k16 = k >> 4;
    int g   = nn & 7, nt = nn >> 3;
    int pos = (((k16*NT + nt)*32) + g*4 + t)*2 + reg;
    g_wfh[base + pos] = h;
    g_wfl[base + pos] = l;
}

// ---------------- init: zero cnt/stats/bar + is64 detect + wsplit(w0,w1,w2) --------
__global__ void k_init(const void* ei, const float* __restrict__ w0,
                       const float* __restrict__ w1, const float* __restrict__ w2, int n){
    int b = blockIdx.x, tid = threadIdx.x;
    int zb = (n + 255) >> 8;                 // blocks dedicated to cnt-zeroing
    if (b < zb){
        int i = b*256 + tid;
        if (i < n) g_cnt[i] = 0;
        if (b == 0){ g_stats[tid] = 0.f; if (tid == 0){ g_done = 0; g_bar = 0; } }
    } else {
        int j = (b - zb)*256 + tid;          // 0..20479 (80 blocks)
        if (j < 8192)       wsplit_one<128>(w0, j,          0);
        else if (j < 16384) wsplit_one<128>(w1, j - 8192,   8192);
        else                wsplit_one<64>(w2, j - 16384,  16384);
        if (b == zb && tid < 32){
            const int* p = (const int*)ei;
            int bad = 0;
            #pragma unroll
            for (int k = tid; k < 128; k += 32) bad |= (p[2*k+1] != 0);
            unsigned m = __ballot_sync(0xffffffffu, bad);
            if (tid == 0) g_is64 = (m == 0);   // ids < 2^31 -> high words zero iff int64
        }
    }
}

// ---------------- FUSED graph build: hist + scan + deg + fill, one kernel ----------
// NB=512 blocks x 512 thr (4 CTAs/SM, single wave; grid barriers safe).
__global__ void __launch_bounds__(512) k_graph(const void* ei, int n, int E){
    __shared__ int sh[512], sh2[512];
    int tid = threadIdx.x, b = blockIdx.x;
    int is64 = g_is64;

    // ---- phase 0: degree histogram (grid-stride, 262144 threads) ----
    for (int e = b*512 + tid; e < E; e += NB*512){
        int d = (int)edge_at(ei, (long long)E + e, is64);
        atomicAdd(&g_cnt[d], 1);
    }
    grid_bar(NB);

    // ---- phase A: per-block chunk sums (PT contiguous nodes per thread) ----
    int CH = CDIV(n, NB);                 // nodes per block (196 for n=100k)
    int PT = CDIV(CH, 512);               // nodes per thread (1 for n=100k)
    int base = b*CH;
    int i0 = base + tid*PT;
    int c0 = 0, c1 = 0;
    if (i0 < n && tid*PT < CH) c0 = g_cnt[i0];
    if (PT > 1 && i0+1 < n && tid*PT+1 < CH) c1 = g_cnt[i0+1];
    sh[tid] = c0 + c1;
    __syncthreads();
    #pragma unroll
    for (int off = 256; off; off >>= 1){
        if (tid < off) sh[tid] += sh[tid + off];
        __syncthreads();
    }
    if (tid == 0) g_bsum[b] = sh[0];
    grid_bar(2*NB);

    // ---- phase B: scan block sums + block-local scan -> rowptr, deg, cnt=0 ----
    sh[tid] = g_bsum[tid];                // NB == blockDim
    __syncthreads();
    #pragma unroll
    for (int off = 1; off < 512; off <<= 1){
        int v = (tid >= off) ? sh[tid - off] : 0;
        __syncthreads();
        sh[tid] += v;
        __syncthreads();
    }
    int blockBase = sh[b] - g_bsum[b];    // exclusive prefix for this block
    __syncthreads();
    sh2[tid] = c0 + c1;
    __syncthreads();
    #pragma unroll
    for (int off = 1; off < 512; off <<= 1){
        int v = (tid >= off) ? sh2[tid - off] : 0;
        __syncthreads();
        sh2[tid] += v;
        __syncthreads();
    }
    int tex = blockBase + sh2[tid] - (c0 + c1);   // exclusive offset for i0
    if (i0 < n && tid*PT < CH){
        g_rowptr[i0] = tex;
        g_cnt[i0] = 0;
        g_dis[i0] = rsqrtf((float)(c0 + 1));      // +1 self loop
        int i1 = i0 + 1;
        if (PT > 1 && i1 < n && tid*PT+1 < CH){
            g_rowptr[i1] = tex + c0;
            g_cnt[i1] = 0;
            g_dis[i1] = rsqrtf((float)(c1 + 1));
        }
    }
    if (b == 0 && tid == 0) g_rowptr[n] = E;
    grid_bar(3*NB);

    // ---- phase C: fill CSR (grid-stride; 4B col only — weights folded into bufB) ----
    for (int e = b*512 + tid; e < E; e += NB*512){
        int s = (int)edge_at(ei, e, is64);
        int d = (int)edge_at(ei, (long long)E + e, is64);
        int pos = g_rowptr[d] + atomicAdd(&g_cnt[d], 1);
        g_ecol[pos] = s;
    }
}

// ---------------- GEMM: bufB = dis[row] * (relu(bn(A)) @ W) via bf16x3 mma.sync ----
// A tile staged as PACKED bf16x2 hi/lo fragments (2 x 128x68 uint, 69.6KB smem),
// converted during the global load; ONE sync; mainloop = pure LDS.32 + MMA.
// D += Ahi*Whi + Ahi*Wlo + Alo*Whi  (fp32 accum; dropped lo*lo ~ 2^-18)
// Epilogue pre-scales each output row by dis[row] (GCN norm factorization).
template<int DOUT, int ASEL, int WBASE>
__global__ void __launch_bounds__(256, 2) k_gemm_bf(const float* __restrict__ Aext, int n){
    constexpr int NT   = DOUT/8;
    constexpr int NTW  = NT/2;                // n-tiles per warp (8 or 4)
    constexpr int LDA2 = 68;                  // uint stride; 68 mod 32 = 4 -> conflict-free
    extern __shared__ unsigned sm[];          // 2 * 128*68*4 = 69632 B
    unsigned* Ahi = sm;
    unsigned* Alo = sm + 128*LDA2;

    const float* A = (ASEL==0) ? Aext : g_bufA;
    int tid = threadIdx.x, lane = tid & 31, warp = tid >> 5;
    int wm = warp >> 1, wn = warp & 1;
    int g = lane >> 2, t = lane & 3;
    int rowBase = blockIdx.x * 128;

    float acc[2][NTW][4];
    #pragma unroll
    for (int a=0;a<2;a++)
        #pragma unroll
        for (int b=0;b<NTW;b++)
            #pragma unroll
            for (int c=0;c<4;c++) acc[a][b][c] = 0.f;

    // ---- full A tile: load, (BN+ReLU), split to packed bf16 hi/lo ----
    #pragma unroll
    for (int i=0;i<16;i++){
        int idx  = tid + i*256;           // 0..4095
        int r    = idx >> 5;              // 0..127
        int c4   = idx & 31;              // float4 within 128 cols
        int grow = rowBase + r;
        float4 v = make_float4(0.f,0.f,0.f,0.f);
        if (grow < n) v = *(const float4*)&A[(size_t)grow*128 + c4*4];
        if (ASEL == 1){
            float4 sc = *(const float4*)&g_scale[c4*4];
            float4 sh = *(const float4*)&g_shift[c4*4];
            v.x = fmaxf(fmaf(v.x, sc.x, sh.x), 0.f);
            v.y = fmaxf(fmaf(v.y, sc.y, sh.y), 0.f);
            v.z = fmaxf(fmaf(v.z, sc.z, sh.z), 0.f);
            v.w = fmaxf(fmaf(v.w, sc.w, sh.w), 0.f);
        }
        unsigned h0 = pack_bf16(v.x, v.y);
        unsigned h1 = pack_bf16(v.z, v.w);
        unsigned l0 = pack_bf16(v.x - bf_lo(h0), v.y - bf_hi(h0));
        unsigned l1 = pack_bf16(v.z - bf_lo(h1), v.w - bf_hi(h1));
        *(uint2*)&Ahi[r*LDA2 + c4*2] = make_uint2(h0, h1);
        *(uint2*)&Alo[r*LDA2 + c4*2] = make_uint2(l0, l1);
    }
    __syncthreads();

    const uint2* WH = (const uint2*)(g_wfh + WBASE);
    const uint2* WL = (const uint2*)(g_wfl + WBASE);

    #pragma unroll
    for (int k16 = 0; k16 < 8; k16++){
        unsigned ah[2][4], al[2][4];
        #pragma unroll
        for (int mt=0; mt<2; mt++){
            int r0 = wm*32 + mt*16 + g;
            #pragma unroll
            for (int q=0; q<4; q++){
                int rr = r0 + (q & 1)*8;
                int ci = k16*8 + t + (q >> 1)*4;
                ah[mt][q] = Ahi[rr*LDA2 + ci];
                al[mt][q] = Alo[rr*LDA2 + ci];
            }
        }
        #pragma unroll
        for (int nt=0; nt<NTW; nt++){
            int off = (k16*NT + wn*NTW + nt)*32 + lane;
            uint2 bh = __ldg(&WH[off]);
            uint2 bl = __ldg(&WL[off]);
            unsigned bhv[2] = {bh.x, bh.y};
            unsigned blv[2] = {bl.x, bl.y};
            #pragma unroll
            for (int mt=0; mt<2; mt++){
                mma_bf16(acc[mt][nt], ah[mt], bhv);
                mma_bf16(acc[mt][nt], ah[mt], blv);
                mma_bf16(acc[mt][nt], al[mt], bhv);
            }
        }
    }

    // ---- store C -> g_bufB, pre-scaled by dis[row] ----
    #pragma unroll
    for (int mt=0; mt<2; mt++){
        int r0 = rowBase + wm*32 + mt*16 + g;
        float d0 = (r0     < n) ? g_dis[r0]     : 0.f;
        float d1 = (r0 + 8 < n) ? g_dis[r0 + 8] : 0.f;
        #pragma unroll
        for (int nt=0; nt<NTW; nt++){
            int col = (wn*NTW + nt)*8 + t*2;
            if (r0 < n)
                *(float2*)&g_bufB[(size_t)r0*DOUT + col] =
                    make_float2(acc[mt][nt][0]*d0, acc[mt][nt][1]*d0);
            if (r0 + 8 < n)
                *(float2*)&g_bufB[(size_t)(r0+8)*DOUT + col] =
                    make_float2(acc[mt][nt][2]*d1, acc[mt][nt][3]*d1);
        }
    }
}

// ---------------- aggregation: PERSISTENT single-wave (6 CTA/SM) + BN stats --------
// out[d] = dis[d] * ( bufB'[d] + sum_s bufB'[s] )  where bufB' is dis-prescaled.
template<int D>
__global__ void __launch_bounds__(256, 6) k_agg(const float* __restrict__ gw,
                                                const float* __restrict__ be, int n){
    constexpr int F   = D/4;        // float4 per row (32 or 16)
    constexpr int NPW = 32/F;       // nodes per warp-slot (1 or 2)
    __shared__ float ss[128], sq[128];
    __shared__ int isLast;
    int tid = threadIdx.x;
    if (tid < D){ ss[tid] = 0.f; sq[tid] = 0.f; }
    __syncthreads();

    int lane  = tid & 31;
    int gwarp = (blockIdx.x*256 + tid) >> 5;
    int nwarp = (gridDim.x*256) >> 5;
    int fi    = lane % F;
    int sub   = lane / F;

    const float4* t = (const float4*)g_bufB;
    float4* o = (float4*)g_bufA;

    float l0=0.f,l1=0.f,l2=0.f,l3=0.f, q0=0.f,q1=0.f,q2=0.f,q3=0.f;

    for (int node = gwarp*NPW + sub; node < n; node += nwarp*NPW){
        float4 acc = t[(size_t)node*F + fi];      // self term (pre-scaled)

        int p0 = g_rowptr[node], p1 = g_rowptr[node+1];
        int p = p0;
        for (; p + 1 < p1; p += 2){
            int s0 = g_ecol[p], s1 = g_ecol[p+1];
            float4 u0 = t[(size_t)s0*F + fi];
            float4 u1 = t[(size_t)s1*F + fi];
            acc.x += u0.x + u1.x;
            acc.y += u0.y + u1.y;
            acc.z += u0.z + u1.z;
            acc.w += u0.w + u1.w;
        }
        if (p < p1){
            int s0 = g_ecol[p];
            float4 u0 = t[(size_t)s0*F + fi];
            acc.x += u0.x; acc.y += u0.y; acc.z += u0.z; acc.w += u0.w;
        }
        float dd = g_dis[node];
        acc.x *= dd; acc.y *= dd; acc.z *= dd; acc.w *= dd;
        o[(size_t)node*F + fi] = acc;

        l0 += acc.x; q0 += acc.x*acc.x;
        l1 += acc.y; q1 += acc.y*acc.y;
        l2 += acc.z; q2 += acc.z*acc.z;
        l3 += acc.w; q3 += acc.w*acc.w;
    }

    int ch = fi*4;
    atomicAdd(&ss[ch+0], l0); atomicAdd(&sq[ch+0], q0);
    atomicAdd(&ss[ch+1], l1); atomicAdd(&sq[ch+1], q1);
    atomicAdd(&ss[ch+2], l2); atomicAdd(&sq[ch+2], q2);
    atomicAdd(&ss[ch+3], l3); atomicAdd(&sq[ch+3], q3);
    __syncthreads();
    if (tid < D){
        atomicAdd(&g_stats[tid],       ss[tid]);
        atomicAdd(&g_stats[128 + tid], sq[tid]);
    }
    __syncthreads();

    // ---- last-block BN finalize (threadfence-reduction pattern) ----
    if (tid == 0){
        __threadfence();
        isLast = (atomicAdd(&g_done, 1) == (int)gridDim.x - 1);
    }
    __syncthreads();
    if (isLast){
        if (tid < D){
            float s = atomicAdd(&g_stats[tid],       0.f);   // coherent read
            float q = atomicAdd(&g_stats[128 + tid], 0.f);
            float inv_n = 1.0f / (float)n;
            float mu  = s * inv_n;
            float var = q * inv_n - mu*mu;
            float sc  = gw[tid] * rsqrtf(var + 1e-5f);
            g_scale[tid] = sc;
            g_shift[tid] = be[tid] - mu*sc;
            g_stats[tid] = 0.f;              // ready for next layer
            g_stats[128 + tid] = 0.f;
        }
        if (tid == 0) g_done = 0;
    }
}

// ---------------- head: 2-layer MLP (reads g_scale/g_shift from agg<64>) -----------
__global__ void __launch_bounds__(256) k_head(const float* __restrict__ wc1,
                                              const float* __restrict__ bc1,
                                              const float* __restrict__ wc2,
                                              const float* __restrict__ bc2,
                                              float* __restrict__ out, int n){
    __shared__ float w1s[64*32];
    __shared__ float b1s[32], w2s[32], scs[64], shs[64];
    int tid = threadIdx.x;
    for (int i = tid; i < 64*32; i += 256) w1s[i] = wc1[i];
    if (tid < 32){ b1s[tid] = bc1[tid]; w2s[tid] = wc2[tid]; }
    if (tid < 64){ scs[tid] = g_scale[tid]; shs[tid] = g_shift[tid]; }
    __syncthreads();

    int warp = (blockIdx.x*256 + tid) >> 5;
    int lane = tid & 31;
    if (warp >= n) return;

    const float* row = &g_bufA[(size_t)warp * 64];
    float a0 = b1s[lane], a1 = 0.f, a2 = 0.f, a3 = 0.f;
    #pragma unroll
    for (int k = 0; k < 64; k += 4){
        float v0 = fmaxf(fmaf(row[k+0], scs[k+0], shs[k+0]), 0.f);
        float v1 = fmaxf(fmaf(row[k+1], scs[k+1], shs[k+1]), 0.f);
        float v2 = fmaxf(fmaf(row[k+2], scs[k+2], shs[k+2]), 0.f);
        float v3 = fmaxf(fmaf(row[k+3], scs[k+3], shs[k+3]), 0.f);
        a0 = fmaf(v0, w1s[(k+0)*32 + lane], a0);
        a1 = fmaf(v1, w1s[(k+1)*32 + lane], a1);
        a2 = fmaf(v2, w1s[(k+2)*32 + lane], a2);
        a3 = fmaf(v3, w1s[(k+3)*32 + lane], a3);
    }
    float h = fmaxf((a0+a1)+(a2+a3), 0.f) * w2s[lane];
    #pragma unroll
    for (int off = 16; off; off >>= 1) h += __shfl_xor_sync(0xffffffff, h, off);
    if (lane == 0) out[warp] = h + bc2[0];
}

// ---------------- launch ----------------
extern "C" void kernel_launch(void* const* d_in, const int* in_sizes, int n_in,
                              void* d_out, int out_size){
    const float* x   = (const float*)d_in[0];
    const void*  ei  = d_in[1];
    const float* w0  = (const float*)d_in[2];
    const float* g0  = (const float*)d_in[4];
    const float* be0 = (const float*)d_in[5];
    const float* w1  = (const float*)d_in[6];
    const float* g1  = (const float*)d_in[8];
    const float* be1 = (const float*)d_in[9];
    const float* w2  = (const float*)d_in[10];
    const float* g2  = (const float*)d_in[12];
    const float* be2 = (const float*)d_in[13];
    const float* wc1 = (const float*)d_in[14];
    const float* bc1 = (const float*)d_in[15];
    const float* wc2 = (const float*)d_in[16];
    const float* bc2 = (const float*)d_in[17];
    float* out = (float*)d_out;

    int n = in_sizes[0] / 128;
    int E = in_sizes[1] / 2;

    const int GSMEM = 2*128*68*4;    // 69632 B
    cudaFuncSetAttribute(k_gemm_bf<128,0,0>,     cudaFuncAttributeMaxDynamicSharedMemorySize, GSMEM);
    cudaFuncSetAttribute(k_gemm_bf<128,1,8192>,  cudaFuncAttributeMaxDynamicSharedMemorySize, GSMEM);
    cudaFuncSetAttribute(k_gemm_bf<64,1,16384>,  cudaFuncAttributeMaxDynamicSharedMemorySize, GSMEM);

    int zb = CDIV(n,256);
    int gemmGrid = CDIV(n, 128);

    // 9 launches, single stream; my #4 = k_agg<128> (ncu -s 5 -c 1 lands there)
    k_init<<<zb + 80, 256>>>(ei, w0, w1, w2, n);                 // 1
    k_graph<<<NB,512>>>(ei, n, E);                               // 2 (hist+scan+deg+fill)
    k_gemm_bf<128,0,0><<<gemmGrid,256,GSMEM>>>(x, n);            // 3 (dis ready: after k_graph)

    // ---- layer 0 ----
    k_agg<128><<<AGG_BLOCKS,256>>>(g0, be0, n);                  // 4 <- profiled

    // ---- layer 1 ----
    k_gemm_bf<128,1,8192><<<gemmGrid,256,GSMEM>>>(nullptr, n);   // 5
    k_agg<128><<<AGG_BLOCKS,256>>>(g1, be1, n);                  // 6

    // ---- layer 2 ----
    k_gemm_bf<64,1,16384><<<gemmGrid,256,GSMEM>>>(nullptr, n);   // 7
    k_agg<64><<<AGG_BLOCKS,256>>>(g2, be2, n);                   // 8

    // ---- head ----
    k_head<<<CDIV(n*32,256),256>>>(wc1, bc1, wc2, bc2, out, n);  // 9
}